// round 8
// baseline (speedup 1.0000x reference)
#include <cuda_runtime.h>
#include <cuda_fp16.h>

#define NCHAN 256
#define NPTS  49

// Channel-interleaved fp16 HWC scratch for image 0, levels 3..5 (11 MB, L2-resident).
// slot(pix, phase, l, k) = pix*256 + phase*128 + 4*l + k  holds original channel
// phase*128 + 32*k + l
#define OFF_L3 0
#define OFF_L4 (16384 * 256)
#define OFF_L5 (OFF_L4 + 4096 * 256)
#define SCRATCH_ELEMS (OFF_L5 + 1024 * 256)
__device__ __align__(16) __half g_scratch[SCRATCH_ELEMS];

// ---- fused CHW(fp32) -> interleaved-HWC(fp16) transpose, levels 3,4,5 ----
__global__ __launch_bounds__(512) void tpose_all(const float* __restrict__ p3,
                                                 const float* __restrict__ p4,
                                                 const float* __restrict__ p5) {
    __shared__ float tile[128][33];
    int b = blockIdx.x;
    const float* in;
    __half* op;
    int HW;
    if (b < 1024)      { in = p3; op = g_scratch + OFF_L3; HW = 16384; }
    else if (b < 1280) { b -= 1024; in = p4; op = g_scratch + OFF_L4; HW = 4096; }
    else               { b -= 1280; in = p5; op = g_scratch + OFF_L5; HW = 1024; }
    int xt    = b >> 1;        // pixel tile (32 px)
    int phase = b & 1;         // channel half

    int tx = threadIdx.x, ty = threadIdx.y;   // 32 x 16
    int x = xt * 32 + tx;
    #pragma unroll
    for (int j = ty; j < 128; j += 16)
        tile[j][tx] = __ldcs(in + (phase * 128 + j) * HW + x);
    __syncthreads();

    int pbase = xt * 32;
    #pragma unroll
    for (int px = ty; px < 32; px += 16) {
        __half2 h01 = __floats2half2_rn(tile[tx      ][px], tile[tx + 32][px]);
        __half2 h23 = __floats2half2_rn(tile[tx + 64 ][px], tile[tx + 96][px]);
        uint2 v;
        v.x = *(unsigned*)&h01;
        v.y = *(unsigned*)&h23;
        *(uint2*)(op + (pbase + px) * NCHAN + phase * 128 + 4 * tx) = v;
    }
}

// ---- pooling: fp16 HWC gathers for levels 3-5, fp32 NCHW path for level 2 ----
__global__ __launch_bounds__(512) void roi_pool(const float* __restrict__ p2,
                                                const float* __restrict__ rois,
                                                float* __restrict__ out) {
    __shared__ __align__(16) float sout[NCHAN * NPTS];  // flat == output layout
    __shared__ int   s_oTL[NPTS], s_oTR[NPTS], s_oBL[NPTS], s_oBR[NPTS];
    __shared__ float s_lx[NPTS], s_ly[NPTS], s_m[NPTS];

    int n   = blockIdx.x;
    int tid = threadIdx.x;

    float rx1 = __ldg(rois + 4 * n + 0);
    float ry1 = __ldg(rois + 4 * n + 1);
    float rx2 = __ldg(rois + 4 * n + 2);
    float ry2 = __ldg(rois + 4 * n + 3);

    float area = (ry2 - ry1) * (rx2 - rx1);
    float lvlf = log2f(sqrtf(fmaxf(area, 0.0f)) / 224.0f);
    int level = (int)rintf(lvlf) + 4;          // half-even, matches jnp.round
    level = min(5, max(2, level));
    int W = 1024 >> level;                     // H == W

    if (tid < NPTS) {
        float scale = (float)(W - 1);
        float ny1 = ry1 * (1.0f / 1024.0f);
        float nx1 = rx1 * (1.0f / 1024.0f);
        float dy  = __fsub_rn(ry2 * (1.0f / 1024.0f), ny1);
        float dx  = __fsub_rn(rx2 * (1.0f / 1024.0f), nx1);

        int py = tid / 7;
        int px = tid - py * 7;

        float ty = (float)py / 6.0f;
        float ys = __fmul_rn(__fadd_rn(ny1, __fmul_rn(ty, dy)), scale);
        bool  vy = (ys >= 0.0f) && (ys <= scale);
        float ysc = fminf(fmaxf(ys, 0.0f), scale);
        int   y0  = (int)floorf(ysc);
        int   y1i = min(y0 + 1, W - 1);
        float ly  = __fsub_rn(ysc, (float)y0);

        float tx = (float)px / 6.0f;
        float xs = __fmul_rn(__fadd_rn(nx1, __fmul_rn(tx, dx)), scale);
        bool  vx = (xs >= 0.0f) && (xs <= scale);
        float xsc = fminf(fmaxf(xs, 0.0f), scale);
        int   x0  = (int)floorf(xsc);
        int   x1i = min(x0 + 1, W - 1);
        float lx  = __fsub_rn(xsc, (float)x0);

        s_oTL[tid] = y0  * W + x0;
        s_oTR[tid] = y0  * W + x1i;
        s_oBL[tid] = y1i * W + x0;
        s_oBR[tid] = y1i * W + x1i;
        s_lx[tid] = lx;
        s_ly[tid] = ly;
        s_m[tid]  = (vy && vx) ? 1.0f : 0.0f;
    }
    __syncthreads();

    long obase = (long)n * (NCHAN * NPTS);

    if (level >= 3) {
        const __half* fm = g_scratch +
            ((level == 3) ? OFF_L3 : (level == 4) ? OFF_L4 : OFF_L5);
        int warpid = tid >> 5;       // 0..15
        int lane   = tid & 31;
        int phase  = warpid >> 3;    // warps 0-7 -> phase 0, 8-15 -> phase 1
        int wslot  = warpid & 7;
        int pbias  = phase * 128 + 4 * lane;
        float* sph = sout + phase * (128 * NPTS);

        #pragma unroll 2
        for (int pt = wslot; pt < NPTS; pt += 8) {
            uint2 tlq = *(const uint2*)(fm + s_oTL[pt] * NCHAN + pbias);
            uint2 trq = *(const uint2*)(fm + s_oTR[pt] * NCHAN + pbias);
            uint2 blq = *(const uint2*)(fm + s_oBL[pt] * NCHAN + pbias);
            uint2 brq = *(const uint2*)(fm + s_oBR[pt] * NCHAN + pbias);
            float lx = s_lx[pt], ly = s_ly[pt], m = s_m[pt];

            float2 tl01 = __half22float2(*(__half2*)&tlq.x);
            float2 tl23 = __half22float2(*(__half2*)&tlq.y);
            float2 tr01 = __half22float2(*(__half2*)&trq.x);
            float2 tr23 = __half22float2(*(__half2*)&trq.y);
            float2 bl01 = __half22float2(*(__half2*)&blq.x);
            float2 bl23 = __half22float2(*(__half2*)&blq.y);
            float2 br01 = __half22float2(*(__half2*)&brq.x);
            float2 br23 = __half22float2(*(__half2*)&brq.y);

            float tl[4] = {tl01.x, tl01.y, tl23.x, tl23.y};
            float tr[4] = {tr01.x, tr01.y, tr23.x, tr23.y};
            float bl[4] = {bl01.x, bl01.y, bl23.x, bl23.y};
            float br[4] = {br01.x, br01.y, br23.x, br23.y};
            #pragma unroll
            for (int k = 0; k < 4; k++) {
                float top = fmaf(tr[k] - tl[k], lx, tl[k]);
                float bot = fmaf(br[k] - bl[k], lx, bl[k]);
                sph[(k * 32 + lane) * NPTS + pt] = fmaf(bot - top, ly, top) * m;
            }
        }
        __syncthreads();

        const float4* s4 = (const float4*)sout;
        float4* o4 = (float4*)(out + obase);
        #pragma unroll
        for (int i = tid; i < NCHAN * NPTS / 4; i += 512)
            __stcs(o4 + i, s4[i]);
    } else {
        // level 2: gather directly from NCHW fp32 p2 (image 0, plane 65536, W=256)
        int pt = tid & 63;   // 49 active
        int cg = tid >> 6;   // 0..7
        if (pt < NPTS) {
            int oTL = s_oTL[pt], oTR = s_oTR[pt], oBL = s_oBL[pt], oBR = s_oBR[pt];
            float lx = s_lx[pt], ly = s_ly[pt], m = s_m[pt];
            #pragma unroll 4
            for (int c = cg; c < NCHAN; c += 8) {
                const float* fc = p2 + c * 65536;
                float tl = __ldg(fc + oTL);
                float tr = __ldg(fc + oTR);
                float bl = __ldg(fc + oBL);
                float br = __ldg(fc + oBR);
                float top = fmaf(tr - tl, lx, tl);
                float bot = fmaf(br - bl, lx, bl);
                __stcs(&out[obase + (long)c * NPTS + pt], fmaf(bot - top, ly, top) * m);
            }
        }
    }
}

extern "C" void kernel_launch(void* const* d_in, const int* in_sizes, int n_in,
                              void* d_out, int out_size) {
    const float* p2   = (const float*)d_in[0];
    const float* p3   = (const float*)d_in[1];
    const float* p4   = (const float*)d_in[2];
    const float* p5   = (const float*)d_in[3];
    const float* rois = (const float*)d_in[4];
    float* out = (float*)d_out;

    tpose_all<<<1344, dim3(32, 16)>>>(p3, p4, p5);

    int nrois = in_sizes[4] / 4;   // B*R
    roi_pool<<<nrois, 512>>>(p2, rois, out);
}

// round 9
// speedup vs baseline: 1.5696x; 1.5696x over previous
#include <cuda_runtime.h>
#include <cuda_fp16.h>

#define NCHAN 256
#define NPTS  49

// fp16 HWC scratch, channel-interleaved so ONE float4 (8 halfs) per lane covers
// all 256 channels per warp: slot(pix, l, k) = pix*256 + 8*l + k  holds channel
// 32*k + l  (l = lane 0..31, k = 0..7). 11 MB total -> L2-resident.
#define OFF_L3 0
#define OFF_L4 (16384 * 256)
#define OFF_L5 (OFF_L4 + 4096 * 256)
#define SCRATCH_ELEMS (OFF_L5 + 1024 * 256)
__device__ __align__(16) __half g_scratch[SCRATCH_ELEMS];

// ---- fused CHW(fp32) -> interleaved-HWC(fp16), levels 3,4,5 (image 0) ----
// block: 32 pixels x all 256 channels. 512 threads. blocks: 512+128+32 = 672.
__global__ __launch_bounds__(512) void tpose_all(const float* __restrict__ p3,
                                                 const float* __restrict__ p4,
                                                 const float* __restrict__ p5) {
    __shared__ float tile[256][33];
    int b = blockIdx.x;
    const float* in;
    __half* op;
    int HW;
    if (b < 512)      { in = p3; op = g_scratch + OFF_L3; HW = 16384; }
    else if (b < 640) { b -= 512; in = p4; op = g_scratch + OFF_L4; HW = 4096; }
    else              { b -= 640; in = p5; op = g_scratch + OFF_L5; HW = 1024; }

    int tx = threadIdx.x, ty = threadIdx.y;   // 32 x 16
    int x = b * 32 + tx;
    #pragma unroll
    for (int j = ty; j < 256; j += 16)
        tile[j][tx] = __ldcs(in + j * HW + x);
    __syncthreads();

    int pbase = b * 32;
    #pragma unroll
    for (int px = ty; px < 32; px += 16) {
        __half2 h01 = __floats2half2_rn(tile[tx      ][px], tile[tx + 32 ][px]);
        __half2 h23 = __floats2half2_rn(tile[tx + 64 ][px], tile[tx + 96 ][px]);
        __half2 h45 = __floats2half2_rn(tile[tx + 128][px], tile[tx + 160][px]);
        __half2 h67 = __floats2half2_rn(tile[tx + 192][px], tile[tx + 224][px]);
        uint4 v;
        v.x = *(unsigned*)&h01;
        v.y = *(unsigned*)&h23;
        v.z = *(unsigned*)&h45;
        v.w = *(unsigned*)&h67;
        *(uint4*)(op + (pbase + px) * NCHAN + 8 * tx) = v;
    }
}

// ---- pooling: one LDG.128 per tap per warp covers 256 channels ----
__global__ __launch_bounds__(512, 2) void roi_pool(const float* __restrict__ p2,
                                                   const float* __restrict__ rois,
                                                   float* __restrict__ out) {
    __shared__ __align__(16) float sout[NCHAN * NPTS];  // flat == output layout
    __shared__ int   s_oTL[NPTS], s_oTR[NPTS], s_oBL[NPTS], s_oBR[NPTS];
    __shared__ float s_lx[NPTS], s_ly[NPTS], s_m[NPTS];

    int n   = blockIdx.x;
    int tid = threadIdx.x;

    float rx1 = __ldg(rois + 4 * n + 0);
    float ry1 = __ldg(rois + 4 * n + 1);
    float rx2 = __ldg(rois + 4 * n + 2);
    float ry2 = __ldg(rois + 4 * n + 3);

    float area = (ry2 - ry1) * (rx2 - rx1);
    float lvlf = log2f(sqrtf(fmaxf(area, 0.0f)) / 224.0f);
    int level = (int)rintf(lvlf) + 4;          // half-even, matches jnp.round
    level = min(5, max(2, level));
    int W = 1024 >> level;                     // H == W

    if (tid < NPTS) {
        float scale = (float)(W - 1);
        float ny1 = ry1 * (1.0f / 1024.0f);
        float nx1 = rx1 * (1.0f / 1024.0f);
        float dy  = __fsub_rn(ry2 * (1.0f / 1024.0f), ny1);
        float dx  = __fsub_rn(rx2 * (1.0f / 1024.0f), nx1);

        int py = tid / 7;
        int px = tid - py * 7;

        float ty = (float)py / 6.0f;
        float ys = __fmul_rn(__fadd_rn(ny1, __fmul_rn(ty, dy)), scale);
        bool  vy = (ys >= 0.0f) && (ys <= scale);
        float ysc = fminf(fmaxf(ys, 0.0f), scale);
        int   y0  = (int)floorf(ysc);
        int   y1i = min(y0 + 1, W - 1);
        float ly  = __fsub_rn(ysc, (float)y0);

        float tx = (float)px / 6.0f;
        float xs = __fmul_rn(__fadd_rn(nx1, __fmul_rn(tx, dx)), scale);
        bool  vx = (xs >= 0.0f) && (xs <= scale);
        float xsc = fminf(fmaxf(xs, 0.0f), scale);
        int   x0  = (int)floorf(xsc);
        int   x1i = min(x0 + 1, W - 1);
        float lx  = __fsub_rn(xsc, (float)x0);

        s_oTL[tid] = y0  * W + x0;
        s_oTR[tid] = y0  * W + x1i;
        s_oBL[tid] = y1i * W + x0;
        s_oBR[tid] = y1i * W + x1i;
        s_lx[tid] = lx;
        s_ly[tid] = ly;
        s_m[tid]  = (vy && vx) ? 1.0f : 0.0f;
    }
    __syncthreads();

    long obase = (long)n * (NCHAN * NPTS);

    if (level >= 3) {
        const __half* fm = g_scratch +
            ((level == 3) ? OFF_L3 : (level == 4) ? OFF_L4 : OFF_L5);
        int warpid = tid >> 5;       // 0..15, each warp owns pts {w, w+16, w+32, ...}
        int lane   = tid & 31;
        int lbias  = 8 * lane;

        #pragma unroll 2
        for (int pt = warpid; pt < NPTS; pt += 16) {
            uint4 tlq = __ldg((const uint4*)(fm + s_oTL[pt] * NCHAN + lbias));
            uint4 trq = __ldg((const uint4*)(fm + s_oTR[pt] * NCHAN + lbias));
            uint4 blq = __ldg((const uint4*)(fm + s_oBL[pt] * NCHAN + lbias));
            uint4 brq = __ldg((const uint4*)(fm + s_oBR[pt] * NCHAN + lbias));
            float lx = s_lx[pt], ly = s_ly[pt], m = s_m[pt];

            const unsigned* tlw = (const unsigned*)&tlq;
            const unsigned* trw = (const unsigned*)&trq;
            const unsigned* blw = (const unsigned*)&blq;
            const unsigned* brw = (const unsigned*)&brq;
            #pragma unroll
            for (int j = 0; j < 4; j++) {          // half2 pair j -> k = 2j, 2j+1
                float2 tl = __half22float2(*(const __half2*)&tlw[j]);
                float2 tr = __half22float2(*(const __half2*)&trw[j]);
                float2 bl = __half22float2(*(const __half2*)&blw[j]);
                float2 br = __half22float2(*(const __half2*)&brw[j]);

                float topx = fmaf(tr.x - tl.x, lx, tl.x);
                float botx = fmaf(br.x - bl.x, lx, bl.x);
                sout[((2 * j) * 32 + lane) * NPTS + pt] = fmaf(botx - topx, ly, topx) * m;

                float topy = fmaf(tr.y - tl.y, lx, tl.y);
                float boty = fmaf(br.y - bl.y, lx, bl.y);
                sout[((2 * j + 1) * 32 + lane) * NPTS + pt] = fmaf(boty - topy, ly, topy) * m;
            }
        }
        __syncthreads();

        const float4* s4 = (const float4*)sout;
        float4* o4 = (float4*)(out + obase);
        #pragma unroll
        for (int i = tid; i < NCHAN * NPTS / 4; i += 512)
            __stcs(o4 + i, s4[i]);
    } else {
        // level 2: gather directly from NCHW fp32 p2 (image 0, plane 65536, W=256)
        int pt = tid & 63;   // 49 active
        int cg = tid >> 6;   // 0..7
        if (pt < NPTS) {
            int oTL = s_oTL[pt], oTR = s_oTR[pt], oBL = s_oBL[pt], oBR = s_oBR[pt];
            float lx = s_lx[pt], ly = s_ly[pt], m = s_m[pt];
            #pragma unroll 4
            for (int c = cg; c < NCHAN; c += 8) {
                const float* fc = p2 + c * 65536;
                float tl = __ldg(fc + oTL);
                float tr = __ldg(fc + oTR);
                float bl = __ldg(fc + oBL);
                float br = __ldg(fc + oBR);
                float top = fmaf(tr - tl, lx, tl);
                float bot = fmaf(br - bl, lx, bl);
                __stcs(&out[obase + (long)c * NPTS + pt], fmaf(bot - top, ly, top) * m);
            }
        }
    }
}

extern "C" void kernel_launch(void* const* d_in, const int* in_sizes, int n_in,
                              void* d_out, int out_size) {
    const float* p2   = (const float*)d_in[0];
    const float* p3   = (const float*)d_in[1];
    const float* p4   = (const float*)d_in[2];
    const float* p5   = (const float*)d_in[3];
    const float* rois = (const float*)d_in[4];
    float* out = (float*)d_out;

    tpose_all<<<672, dim3(32, 16)>>>(p3, p4, p5);

    int nrois = in_sizes[4] / 4;   // B*R
    roi_pool<<<nrois, 512>>>(p2, rois, out);
}

// round 10
// speedup vs baseline: 1.6418x; 1.0461x over previous
#include <cuda_runtime.h>
#include <cuda_fp16.h>

#define NCHAN 256
#define NPTS  49
#define NTP   672   // tpose tiles: 512 (L3) + 128 (L4) + 32 (L5)

// fp16 HWC scratch, channel-interleaved so ONE float4 (8 halfs) per lane covers
// all 256 channels per warp: slot(pix, l, k) = pix*256 + 8*l + k  holds channel
// 32*k + l. 11 MB -> L2-resident.
#define OFF_L3 0
#define OFF_L4 (16384 * 256)
#define OFF_L5 (OFF_L4 + 4096 * 256)
#define SCRATCH_ELEMS (OFF_L5 + 1024 * 256)
__device__ __align__(16) __half g_scratch[SCRATCH_ELEMS];

__device__ __forceinline__ int roi_level_of(const float* rois, int n,
                                            float& rx1, float& ry1,
                                            float& rx2, float& ry2) {
    rx1 = __ldg(rois + 4 * n + 0);
    ry1 = __ldg(rois + 4 * n + 1);
    rx2 = __ldg(rois + 4 * n + 2);
    ry2 = __ldg(rois + 4 * n + 3);
    float area = (ry2 - ry1) * (rx2 - rx1);
    float lvlf = log2f(sqrtf(fmaxf(area, 0.0f)) / 224.0f);
    int level = (int)rintf(lvlf) + 4;          // half-even, matches jnp.round
    return min(5, max(2, level));
}

// ---- kernel 1: tpose tiles (blocks 0..671) + level-2 NCHW pooling (blocks 672+) ----
// These two block families are fully independent: level-2 pooling reads p2 only.
__global__ __launch_bounds__(512) void tpose_lvl2(const float* __restrict__ p2,
                                                  const float* __restrict__ p3,
                                                  const float* __restrict__ p4,
                                                  const float* __restrict__ p5,
                                                  const float* __restrict__ rois,
                                                  float* __restrict__ out) {
    int b = blockIdx.x;
    if (b < NTP) {
        // ---- CHW(fp32) -> interleaved-HWC(fp16) transpose tile ----
        __shared__ float tile[256][33];
        const float* in;
        __half* op;
        int HW;
        if (b < 512)      { in = p3; op = g_scratch + OFF_L3; HW = 16384; }
        else if (b < 640) { b -= 512; in = p4; op = g_scratch + OFF_L4; HW = 4096; }
        else              { b -= 640; in = p5; op = g_scratch + OFF_L5; HW = 1024; }

        int tx = threadIdx.x & 31, ty = threadIdx.x >> 5;  // 32 x 16
        int x = b * 32 + tx;
        #pragma unroll
        for (int j = ty; j < 256; j += 16)
            tile[j][tx] = __ldcs(in + j * HW + x);
        __syncthreads();

        int pbase = b * 32;
        #pragma unroll
        for (int px = ty; px < 32; px += 16) {
            __half2 h01 = __floats2half2_rn(tile[tx      ][px], tile[tx + 32 ][px]);
            __half2 h23 = __floats2half2_rn(tile[tx + 64 ][px], tile[tx + 96 ][px]);
            __half2 h45 = __floats2half2_rn(tile[tx + 128][px], tile[tx + 160][px]);
            __half2 h67 = __floats2half2_rn(tile[tx + 192][px], tile[tx + 224][px]);
            uint4 v;
            v.x = *(unsigned*)&h01;
            v.y = *(unsigned*)&h23;
            v.z = *(unsigned*)&h45;
            v.w = *(unsigned*)&h67;
            *(uint4*)(op + (pbase + px) * NCHAN + 8 * tx) = v;
        }
        return;
    }

    // ---- level-2 roi: pool directly from NCHW fp32 p2 (image 0, W=256) ----
    int n = b - NTP;
    float rx1, ry1, rx2, ry2;
    if (roi_level_of(rois, n, rx1, ry1, rx2, ry2) != 2) return;

    __shared__ int   s_oTL[64], s_oTR[64], s_oBL[64], s_oBR[64];
    __shared__ float s_lx[64], s_ly[64], s_m[64];

    int tid = threadIdx.x;
    const int W = 256;
    if (tid < NPTS) {
        float scale = (float)(W - 1);
        float ny1 = ry1 * (1.0f / 1024.0f);
        float nx1 = rx1 * (1.0f / 1024.0f);
        float dy  = __fsub_rn(ry2 * (1.0f / 1024.0f), ny1);
        float dx  = __fsub_rn(rx2 * (1.0f / 1024.0f), nx1);

        int py = tid / 7;
        int px = tid - py * 7;

        float ty = (float)py / 6.0f;
        float ys = __fmul_rn(__fadd_rn(ny1, __fmul_rn(ty, dy)), scale);
        bool  vy = (ys >= 0.0f) && (ys <= scale);
        float ysc = fminf(fmaxf(ys, 0.0f), scale);
        int   y0  = (int)floorf(ysc);
        int   y1i = min(y0 + 1, W - 1);
        float ly  = __fsub_rn(ysc, (float)y0);

        float tx = (float)px / 6.0f;
        float xs = __fmul_rn(__fadd_rn(nx1, __fmul_rn(tx, dx)), scale);
        bool  vx = (xs >= 0.0f) && (xs <= scale);
        float xsc = fminf(fmaxf(xs, 0.0f), scale);
        int   x0  = (int)floorf(xsc);
        int   x1i = min(x0 + 1, W - 1);
        float lx  = __fsub_rn(xsc, (float)x0);

        s_oTL[tid] = y0  * W + x0;
        s_oTR[tid] = y0  * W + x1i;
        s_oBL[tid] = y1i * W + x0;
        s_oBR[tid] = y1i * W + x1i;
        s_lx[tid] = lx;
        s_ly[tid] = ly;
        s_m[tid]  = (vy && vx) ? 1.0f : 0.0f;
    }
    __syncthreads();

    long obase = (long)n * (NCHAN * NPTS);
    int pt = tid & 63;   // 49 active
    int cg = tid >> 6;   // 0..7
    if (pt < NPTS) {
        int oTL = s_oTL[pt], oTR = s_oTR[pt], oBL = s_oBL[pt], oBR = s_oBR[pt];
        float lx = s_lx[pt], ly = s_ly[pt], m = s_m[pt];
        #pragma unroll 4
        for (int c = cg; c < NCHAN; c += 8) {
            const float* fc = p2 + c * 65536;
            float tl = __ldg(fc + oTL);
            float tr = __ldg(fc + oTR);
            float bl = __ldg(fc + oBL);
            float br = __ldg(fc + oBR);
            float top = fmaf(tr - tl, lx, tl);
            float bot = fmaf(br - bl, lx, bl);
            __stcs(&out[obase + (long)c * NPTS + pt], fmaf(bot - top, ly, top) * m);
        }
    }
}

// ---- kernel 2: levels 3-5 pooling from fp16 interleaved scratch ----
__global__ __launch_bounds__(384, 3) void roi_pool35(const float* __restrict__ rois,
                                                     float* __restrict__ out) {
    int n = blockIdx.x;
    float rx1, ry1, rx2, ry2;
    int level = roi_level_of(rois, n, rx1, ry1, rx2, ry2);
    if (level == 2) return;

    __shared__ __align__(16) float sout[NCHAN * NPTS];  // flat == output layout
    __shared__ int   s_oTL[NPTS], s_oTR[NPTS], s_oBL[NPTS], s_oBR[NPTS];
    __shared__ float s_lx[NPTS], s_ly[NPTS], s_m[NPTS];

    int tid = threadIdx.x;
    int W = 1024 >> level;

    if (tid < NPTS) {
        float scale = (float)(W - 1);
        float ny1 = ry1 * (1.0f / 1024.0f);
        float nx1 = rx1 * (1.0f / 1024.0f);
        float dy  = __fsub_rn(ry2 * (1.0f / 1024.0f), ny1);
        float dx  = __fsub_rn(rx2 * (1.0f / 1024.0f), nx1);

        int py = tid / 7;
        int px = tid - py * 7;

        float ty = (float)py / 6.0f;
        float ys = __fmul_rn(__fadd_rn(ny1, __fmul_rn(ty, dy)), scale);
        bool  vy = (ys >= 0.0f) && (ys <= scale);
        float ysc = fminf(fmaxf(ys, 0.0f), scale);
        int   y0  = (int)floorf(ysc);
        int   y1i = min(y0 + 1, W - 1);
        float ly  = __fsub_rn(ysc, (float)y0);

        float tx = (float)px / 6.0f;
        float xs = __fmul_rn(__fadd_rn(nx1, __fmul_rn(tx, dx)), scale);
        bool  vx = (xs >= 0.0f) && (xs <= scale);
        float xsc = fminf(fmaxf(xs, 0.0f), scale);
        int   x0  = (int)floorf(xsc);
        int   x1i = min(x0 + 1, W - 1);
        float lx  = __fsub_rn(xsc, (float)x0);

        s_oTL[tid] = y0  * W + x0;
        s_oTR[tid] = y0  * W + x1i;
        s_oBL[tid] = y1i * W + x0;
        s_oBR[tid] = y1i * W + x1i;
        s_lx[tid] = lx;
        s_ly[tid] = ly;
        s_m[tid]  = (vy && vx) ? 1.0f : 0.0f;
    }
    __syncthreads();

    long obase = (long)n * (NCHAN * NPTS);
    const __half* fm = g_scratch +
        ((level == 3) ? OFF_L3 : (level == 4) ? OFF_L4 : OFF_L5);
    int warpid = tid >> 5;       // 0..11, pts stride 12
    int lane   = tid & 31;
    int lbias  = 8 * lane;

    #pragma unroll 4
    for (int pt = warpid; pt < NPTS; pt += 12) {
        uint4 tlq = __ldg((const uint4*)(fm + s_oTL[pt] * NCHAN + lbias));
        uint4 trq = __ldg((const uint4*)(fm + s_oTR[pt] * NCHAN + lbias));
        uint4 blq = __ldg((const uint4*)(fm + s_oBL[pt] * NCHAN + lbias));
        uint4 brq = __ldg((const uint4*)(fm + s_oBR[pt] * NCHAN + lbias));
        float lx = s_lx[pt], ly = s_ly[pt], m = s_m[pt];

        const unsigned* tlw = (const unsigned*)&tlq;
        const unsigned* trw = (const unsigned*)&trq;
        const unsigned* blw = (const unsigned*)&blq;
        const unsigned* brw = (const unsigned*)&brq;
        #pragma unroll
        for (int j = 0; j < 4; j++) {          // half2 pair j -> k = 2j, 2j+1
            float2 tl = __half22float2(*(const __half2*)&tlw[j]);
            float2 tr = __half22float2(*(const __half2*)&trw[j]);
            float2 bl = __half22float2(*(const __half2*)&blw[j]);
            float2 br = __half22float2(*(const __half2*)&brw[j]);

            float topx = fmaf(tr.x - tl.x, lx, tl.x);
            float botx = fmaf(br.x - bl.x, lx, bl.x);
            sout[((2 * j) * 32 + lane) * NPTS + pt] = fmaf(botx - topx, ly, topx) * m;

            float topy = fmaf(tr.y - tl.y, lx, tl.y);
            float boty = fmaf(br.y - bl.y, lx, bl.y);
            sout[((2 * j + 1) * 32 + lane) * NPTS + pt] = fmaf(boty - topy, ly, topy) * m;
        }
    }
    __syncthreads();

    const float4* s4 = (const float4*)sout;
    float4* o4 = (float4*)(out + obase);
    for (int i = tid; i < NCHAN * NPTS / 4; i += 384)
        __stcs(o4 + i, s4[i]);
}

extern "C" void kernel_launch(void* const* d_in, const int* in_sizes, int n_in,
                              void* d_out, int out_size) {
    const float* p2   = (const float*)d_in[0];
    const float* p3   = (const float*)d_in[1];
    const float* p4   = (const float*)d_in[2];
    const float* p5   = (const float*)d_in[3];
    const float* rois = (const float*)d_in[4];
    float* out = (float*)d_out;

    int nrois = in_sizes[4] / 4;   // B*R

    tpose_lvl2<<<NTP + nrois, 512>>>(p2, p3, p4, p5, rois, out);
    roi_pool35<<<nrois, 384>>>(rois, out);
}

// round 11
// speedup vs baseline: 1.9864x; 1.2098x over previous
#include <cuda_runtime.h>
#include <cuda_fp16.h>

#define NCHAN 256
#define NPTS  49

// fp16 HWC scratch for image 0 of ALL levels 2..5, channel-interleaved so ONE
// float4 (8 halfs) per lane covers 256 channels per warp:
// slot(pix, l, k) = pix*256 + 8*l + k  holds channel 32*k + l.  44.6 MB total.
#define OFF_L2 0
#define OFF_L3 (65536 * 256)
#define OFF_L4 (OFF_L3 + 16384 * 256)
#define OFF_L5 (OFF_L4 + 4096 * 256)
#define SCRATCH_ELEMS (OFF_L5 + 1024 * 256)
__device__ __align__(16) __half g_scratch[SCRATCH_ELEMS];

// ---- fused CHW(fp32) -> interleaved-HWC(fp16), levels 2..5 (image 0) ----
// block: 32 pixels x 256 channels, 512 threads.
// tiles: L2 = 2048, L3 = 512, L4 = 128, L5 = 32  -> 2720 blocks
__global__ __launch_bounds__(512) void tpose_all(const float* __restrict__ p2,
                                                 const float* __restrict__ p3,
                                                 const float* __restrict__ p4,
                                                 const float* __restrict__ p5) {
    __shared__ float tile[256][33];
    int b = blockIdx.x;
    const float* in;
    __half* op;
    int HW;
    if (b < 2048)      { in = p2; op = g_scratch + OFF_L2; HW = 65536; }
    else if (b < 2560) { b -= 2048; in = p3; op = g_scratch + OFF_L3; HW = 16384; }
    else if (b < 2688) { b -= 2560; in = p4; op = g_scratch + OFF_L4; HW = 4096; }
    else               { b -= 2688; in = p5; op = g_scratch + OFF_L5; HW = 1024; }

    int tx = threadIdx.x & 31, ty = threadIdx.x >> 5;  // 32 x 16
    int x = b * 32 + tx;
    #pragma unroll
    for (int j = ty; j < 256; j += 16)
        tile[j][tx] = __ldcs(in + j * HW + x);
    __syncthreads();

    int pbase = b * 32;
    #pragma unroll
    for (int px = ty; px < 32; px += 16) {
        __half2 h01 = __floats2half2_rn(tile[tx      ][px], tile[tx + 32 ][px]);
        __half2 h23 = __floats2half2_rn(tile[tx + 64 ][px], tile[tx + 96 ][px]);
        __half2 h45 = __floats2half2_rn(tile[tx + 128][px], tile[tx + 160][px]);
        __half2 h67 = __floats2half2_rn(tile[tx + 192][px], tile[tx + 224][px]);
        uint4 v;
        v.x = *(unsigned*)&h01;
        v.y = *(unsigned*)&h23;
        v.z = *(unsigned*)&h45;
        v.w = *(unsigned*)&h67;
        *(uint4*)(op + (pbase + px) * NCHAN + 8 * tx) = v;
    }
}

// ---- pooling: uniform fp16-HWC fast path for ALL levels ----
__global__ __launch_bounds__(384, 3) void roi_pool(const float* __restrict__ rois,
                                                   float* __restrict__ out) {
    __shared__ __align__(16) float sout[NCHAN * NPTS];  // flat == output layout
    __shared__ int   s_oTL[NPTS], s_oTR[NPTS], s_oBL[NPTS], s_oBR[NPTS];
    __shared__ float s_lx[NPTS], s_ly[NPTS], s_m[NPTS];

    int n   = blockIdx.x;
    int tid = threadIdx.x;

    float rx1 = __ldg(rois + 4 * n + 0);
    float ry1 = __ldg(rois + 4 * n + 1);
    float rx2 = __ldg(rois + 4 * n + 2);
    float ry2 = __ldg(rois + 4 * n + 3);

    float area = (ry2 - ry1) * (rx2 - rx1);
    float lvlf = log2f(sqrtf(fmaxf(area, 0.0f)) / 224.0f);
    int level = (int)rintf(lvlf) + 4;          // half-even, matches jnp.round
    level = min(5, max(2, level));
    int W = 1024 >> level;                     // H == W

    if (tid < NPTS) {
        float scale = (float)(W - 1);
        float ny1 = ry1 * (1.0f / 1024.0f);
        float nx1 = rx1 * (1.0f / 1024.0f);
        float dy  = __fsub_rn(ry2 * (1.0f / 1024.0f), ny1);
        float dx  = __fsub_rn(rx2 * (1.0f / 1024.0f), nx1);

        int py = tid / 7;
        int px = tid - py * 7;

        float ty = (float)py / 6.0f;
        float ys = __fmul_rn(__fadd_rn(ny1, __fmul_rn(ty, dy)), scale);
        bool  vy = (ys >= 0.0f) && (ys <= scale);
        float ysc = fminf(fmaxf(ys, 0.0f), scale);
        int   y0  = (int)floorf(ysc);
        int   y1i = min(y0 + 1, W - 1);
        float ly  = __fsub_rn(ysc, (float)y0);

        float tx = (float)px / 6.0f;
        float xs = __fmul_rn(__fadd_rn(nx1, __fmul_rn(tx, dx)), scale);
        bool  vx = (xs >= 0.0f) && (xs <= scale);
        float xsc = fminf(fmaxf(xs, 0.0f), scale);
        int   x0  = (int)floorf(xsc);
        int   x1i = min(x0 + 1, W - 1);
        float lx  = __fsub_rn(xsc, (float)x0);

        s_oTL[tid] = y0  * W + x0;
        s_oTR[tid] = y0  * W + x1i;
        s_oBL[tid] = y1i * W + x0;
        s_oBR[tid] = y1i * W + x1i;
        s_lx[tid] = lx;
        s_ly[tid] = ly;
        s_m[tid]  = (vy && vx) ? 1.0f : 0.0f;
    }
    __syncthreads();

    long obase = (long)n * (NCHAN * NPTS);
    const __half* fm = g_scratch +
        ((level == 2) ? OFF_L2 : (level == 3) ? OFF_L3 :
         (level == 4) ? OFF_L4 : OFF_L5);
    int warpid = tid >> 5;       // 0..11, pts stride 12
    int lane   = tid & 31;
    int lbias  = 8 * lane;

    #pragma unroll 4
    for (int pt = warpid; pt < NPTS; pt += 12) {
        uint4 tlq = __ldg((const uint4*)(fm + s_oTL[pt] * NCHAN + lbias));
        uint4 trq = __ldg((const uint4*)(fm + s_oTR[pt] * NCHAN + lbias));
        uint4 blq = __ldg((const uint4*)(fm + s_oBL[pt] * NCHAN + lbias));
        uint4 brq = __ldg((const uint4*)(fm + s_oBR[pt] * NCHAN + lbias));
        float lx = s_lx[pt], ly = s_ly[pt], m = s_m[pt];

        const unsigned* tlw = (const unsigned*)&tlq;
        const unsigned* trw = (const unsigned*)&trq;
        const unsigned* blw = (const unsigned*)&blq;
        const unsigned* brw = (const unsigned*)&brq;
        #pragma unroll
        for (int j = 0; j < 4; j++) {          // half2 pair j -> k = 2j, 2j+1
            float2 tl = __half22float2(*(const __half2*)&tlw[j]);
            float2 tr = __half22float2(*(const __half2*)&trw[j]);
            float2 bl = __half22float2(*(const __half2*)&blw[j]);
            float2 br = __half22float2(*(const __half2*)&brw[j]);

            float topx = fmaf(tr.x - tl.x, lx, tl.x);
            float botx = fmaf(br.x - bl.x, lx, bl.x);
            sout[((2 * j) * 32 + lane) * NPTS + pt] = fmaf(botx - topx, ly, topx) * m;

            float topy = fmaf(tr.y - tl.y, lx, tl.y);
            float boty = fmaf(br.y - bl.y, lx, bl.y);
            sout[((2 * j + 1) * 32 + lane) * NPTS + pt] = fmaf(boty - topy, ly, topy) * m;
        }
    }
    __syncthreads();

    const float4* s4 = (const float4*)sout;
    float4* o4 = (float4*)(out + obase);
    for (int i = tid; i < NCHAN * NPTS / 4; i += 384)
        __stcs(o4 + i, s4[i]);
}

extern "C" void kernel_launch(void* const* d_in, const int* in_sizes, int n_in,
                              void* d_out, int out_size) {
    const float* p2   = (const float*)d_in[0];
    const float* p3   = (const float*)d_in[1];
    const float* p4   = (const float*)d_in[2];
    const float* p5   = (const float*)d_in[3];
    const float* rois = (const float*)d_in[4];
    float* out = (float*)d_out;

    int nrois = in_sizes[4] / 4;   // B*R

    tpose_all<<<2720, 512>>>(p2, p3, p4, p5);
    roi_pool<<<nrois, 384>>>(rois, out);
}